// round 5
// baseline (speedup 1.0000x reference)
#include <cuda_runtime.h>

// ---------------- problem constants ----------------
#define B_    2
#define S_    2048
#define E_    2048
#define H_    16
#define HKV_  8
#define D_    64
#define M_    (B_ * S_)            // 4096 token rows
#define LAMBDA_INIT_F 0.78360576653f
#define ONE_MINUS_LI  0.21639423347f
#define SCALE_F       0.125f

// ---------------- scratch (device globals: no allocations allowed) ----------------
__device__ float g_q[M_ * 2048];   // (B,S,2H,D) flattened
__device__ float g_k[M_ * 1024];   // (B,S,2HKV,D)
__device__ float g_v[M_ * 1024];   // (B,S,HKV,2D)
__device__ float g_a[M_ * 2048];   // normalized diff-attn output (B,S,E)
__device__ float g_lam;

// ---------------- fast exp (FMA pipe, no MUFU) ----------------
// exp(x) for x <= 0 (softmax args). ~2e-6 rel error. Handles -1e30 -> ~0.
__device__ __forceinline__ float fexp(float x) {
    x = fmaxf(x, -80.0f);
    float y  = x * 1.44269504088896f;          // x * log2(e)
    float t  = y + 12582912.0f;                // round-to-nearest magic (1.5*2^23)
    int   e  = __float_as_int(t);              // integer part in low bits
    float f  = y - (t - 12582912.0f);          // f in [-0.5, 0.5]
    float p  = 1.33335581e-3f;
    p = fmaf(p, f, 9.61812911e-3f);
    p = fmaf(p, f, 5.55041087e-2f);
    p = fmaf(p, f, 2.40226507e-1f);
    p = fmaf(p, f, 6.93147181e-1f);
    p = fmaf(p, f, 1.0f);
    return __int_as_float(__float_as_int(p) + (e << 23));   // high bits of e shift out
}

// ---------------- SGEMM: C[M,N] = A[M,K] @ W[N,K]^T  (row-major) ----------------
// BM=BN=128, BK=16, 256 threads, 8x8 microtile. M%128==0, N%128==0, K%16==0.
__global__ void __launch_bounds__(256) sgemm_nt(const float* __restrict__ A,
                                                const float* __restrict__ W,
                                                float* __restrict__ C,
                                                int M, int N, int K) {
    __shared__ float As[16][132];
    __shared__ float Bs[16][132];
    const int bm = blockIdx.y * 128;
    const int bn = blockIdx.x * 128;
    const int tid = threadIdx.x;
    const int tx = tid & 15, ty = tid >> 4;

    const int lrow = tid >> 2;           // 0..63
    const int lk4  = (tid & 3) * 4;      // 0,4,8,12
    const float* Ap = A + (size_t)(bm + lrow) * K + lk4;
    const float* Wp = W + (size_t)(bn + lrow) * K + lk4;

    float acc[8][8];
#pragma unroll
    for (int i = 0; i < 8; i++)
#pragma unroll
        for (int j = 0; j < 8; j++) acc[i][j] = 0.0f;

    for (int k0 = 0; k0 < K; k0 += 16) {
        float4 a0 = *(const float4*)(Ap);
        float4 a1 = *(const float4*)(Ap + (size_t)64 * K);
        float4 b0 = *(const float4*)(Wp);
        float4 b1 = *(const float4*)(Wp + (size_t)64 * K);
        __syncthreads();
        As[lk4 + 0][lrow] = a0.x; As[lk4 + 1][lrow] = a0.y;
        As[lk4 + 2][lrow] = a0.z; As[lk4 + 3][lrow] = a0.w;
        As[lk4 + 0][lrow + 64] = a1.x; As[lk4 + 1][lrow + 64] = a1.y;
        As[lk4 + 2][lrow + 64] = a1.z; As[lk4 + 3][lrow + 64] = a1.w;
        Bs[lk4 + 0][lrow] = b0.x; Bs[lk4 + 1][lrow] = b0.y;
        Bs[lk4 + 2][lrow] = b0.z; Bs[lk4 + 3][lrow] = b0.w;
        Bs[lk4 + 0][lrow + 64] = b1.x; Bs[lk4 + 1][lrow + 64] = b1.y;
        Bs[lk4 + 2][lrow + 64] = b1.z; Bs[lk4 + 3][lrow + 64] = b1.w;
        __syncthreads();
#pragma unroll
        for (int kk = 0; kk < 16; kk++) {
            float ra[8], rb[8];
            *(float4*)&ra[0] = *(float4*)&As[kk][ty * 8];
            *(float4*)&ra[4] = *(float4*)&As[kk][ty * 8 + 4];
            *(float4*)&rb[0] = *(float4*)&Bs[kk][tx * 8];
            *(float4*)&rb[4] = *(float4*)&Bs[kk][tx * 8 + 4];
#pragma unroll
            for (int i = 0; i < 8; i++)
#pragma unroll
                for (int j = 0; j < 8; j++)
                    acc[i][j] = fmaf(ra[i], rb[j], acc[i][j]);
        }
        Ap += 16; Wp += 16;
    }

#pragma unroll
    for (int i = 0; i < 8; i++) {
        float* cp = C + (size_t)(bm + ty * 8 + i) * N + bn + tx * 8;
        float4 o0 = make_float4(acc[i][0], acc[i][1], acc[i][2], acc[i][3]);
        float4 o1 = make_float4(acc[i][4], acc[i][5], acc[i][6], acc[i][7]);
        *(float4*)cp = o0;
        *(float4*)(cp + 4) = o1;
    }
}

// ---------------- interleaved RoPE on q (32 heads) and k (16 heads), in place ----------------
#define QPAIRS (M_ * 32 * 32)   // 4194304
#define KPAIRS (M_ * 16 * 32)   // 2097152
__global__ void rope_kernel(const float* __restrict__ cosb, const float* __restrict__ sinb) {
    int idx = blockIdx.x * blockDim.x + threadIdx.x;
    if (idx < QPAIRS) {
        int i = idx & 31;
        int head = (idx >> 5) & 31;
        int t = idx >> 10;
        int s = t & (S_ - 1);
        float c = cosb[s * 32 + i], sn = sinb[s * 32 + i];
        float* p = g_q + (size_t)t * 2048 + head * 64 + 2 * i;
        float x1 = p[0], x2 = p[1];
        p[0] = x1 * c - x2 * sn;
        p[1] = x1 * sn + x2 * c;
    } else if (idx < QPAIRS + KPAIRS) {
        int j = idx - QPAIRS;
        int i = j & 31;
        int head = (j >> 5) & 15;
        int t = j >> 9;
        int s = t & (S_ - 1);
        float c = cosb[s * 32 + i], sn = sinb[s * 32 + i];
        float* p = g_k + (size_t)t * 1024 + head * 64 + 2 * i;
        float x1 = p[0], x2 = p[1];
        p[0] = x1 * c - x2 * sn;
        p[1] = x1 * sn + x2 * c;
    }
}

// ---------------- lambda scalar ----------------
__global__ void lam_kernel(const float* __restrict__ lq1, const float* __restrict__ lk1,
                           const float* __restrict__ lq2, const float* __restrict__ lk2) {
    __shared__ float s1a[2], s2a[2];
    int t = threadIdx.x;   // 64 threads
    float p1 = lq1[t] * lk1[t];
    float p2 = lq2[t] * lk2[t];
#pragma unroll
    for (int o = 16; o > 0; o >>= 1) {
        p1 += __shfl_xor_sync(0xffffffffu, p1, o);
        p2 += __shfl_xor_sync(0xffffffffu, p2, o);
    }
    if ((t & 31) == 0) { s1a[t >> 5] = p1; s2a[t >> 5] = p2; }
    __syncthreads();
    if (t == 0)
        g_lam = expf(s1a[0] + s1a[1]) - expf(s2a[0] + s2a[1]) + LAMBDA_INIT_F;
}

// ---------------- dual-component causal flash attention + diff + RMS-subln ----------------
// grid (S/64, H, B), 256 threads, BQ=BK=64. Thread grid 16x16; S microtile 4x4; O microtile 4x8.
// smem (floats): sQ [2][64][68]=8704 | union{ Kt [2][64][68]=8704 ; P [2][64][65]=8320 } | sV [64][128]=8192
__device__ __forceinline__ void softmax_update(float s[4][4], float m[4], float l[4],
                                               float acc[4][8], bool diag,
                                               int qrow0, int kcol0) {
#pragma unroll
    for (int i = 0; i < 4; i++) {
        float rowm = -1e30f;
#pragma unroll
        for (int j = 0; j < 4; j++) {
            float v = s[i][j] * SCALE_F;
            if (diag && (kcol0 + j > qrow0 + i)) v = -1e30f;
            s[i][j] = v;
            rowm = fmaxf(rowm, v);
        }
        rowm = fmaxf(rowm, __shfl_xor_sync(0xffffffffu, rowm, 1));
        rowm = fmaxf(rowm, __shfl_xor_sync(0xffffffffu, rowm, 2));
        rowm = fmaxf(rowm, __shfl_xor_sync(0xffffffffu, rowm, 4));
        rowm = fmaxf(rowm, __shfl_xor_sync(0xffffffffu, rowm, 8));
        float mnew = fmaxf(m[i], rowm);
        float corr = fexp(m[i] - mnew);
        m[i] = mnew;
        float rs = 0.0f;
#pragma unroll
        for (int j = 0; j < 4; j++) {
            float p = fexp(s[i][j] - mnew);
            s[i][j] = p;
            rs += p;
        }
        rs += __shfl_xor_sync(0xffffffffu, rs, 1);
        rs += __shfl_xor_sync(0xffffffffu, rs, 2);
        rs += __shfl_xor_sync(0xffffffffu, rs, 4);
        rs += __shfl_xor_sync(0xffffffffu, rs, 8);
        l[i] = l[i] * corr + rs;
#pragma unroll
        for (int jj = 0; jj < 8; jj++) acc[i][jj] *= corr;
    }
}

__global__ void __launch_bounds__(256, 1)
diffattn_kernel(const float* __restrict__ subw) {
    extern __shared__ float smem[];
    float* sQ  = smem;                 // [comp*4352 + d*68 + r]
    float* sKP = smem + 8704;          // K: [comp*4352 + d*68 + c] ; P: [comp*4160 + r*65 + c]
    float* sV  = smem + 17408;         // [c*128 + dv]

    const int qt = blockIdx.x, h = blockIdx.y, b = blockIdx.z;
    const int q0 = qt * 64;
    const int kvh = h >> 1;
    const int tid = threadIdx.x;
    const int tx = tid & 15, ty = tid >> 4;
    const float lam = g_lam;

    // load Q tile (both components), transposed [d][r]
#pragma unroll
    for (int comp = 0; comp < 2; comp++) {
        const float* qp = g_q + (size_t)(b * S_ + q0) * 2048 + (2 * h + comp) * 64;
#pragma unroll
        for (int it = 0; it < 16; it++) {
            int idx = tid + it * 256;
            int r = idx >> 6, d = idx & 63;
            sQ[comp * 4352 + d * 68 + r] = qp[(size_t)r * 2048 + d];
        }
    }

    float acc1[4][8], acc2[4][8];
    float m1[4], l1[4], m2[4], l2[4];
#pragma unroll
    for (int i = 0; i < 4; i++) {
        m1[i] = m2[i] = -1e30f;
        l1[i] = l2[i] = 0.0f;
#pragma unroll
        for (int jj = 0; jj < 8; jj++) { acc1[i][jj] = 0.0f; acc2[i][jj] = 0.0f; }
    }

    for (int kt = 0; kt <= qt; kt++) {
        const int k0 = kt * 64;
        __syncthreads();   // previous PV reads done before overwriting sKP/sV
        // load K tile (both components), transposed [d][c]
#pragma unroll
        for (int comp = 0; comp < 2; comp++) {
            const float* kp = g_k + (size_t)(b * S_ + k0) * 1024 + (2 * kvh + comp) * 64;
#pragma unroll
            for (int it = 0; it < 16; it++) {
                int idx = tid + it * 256;
                int c = idx >> 6, d = idx & 63;
                sKP[comp * 4352 + d * 68 + c] = kp[(size_t)c * 1024 + d];
            }
        }
        // load V tile [c][dv], 128 wide
        {
            const float* vp = g_v + (size_t)(b * S_ + k0) * 1024 + kvh * 128;
#pragma unroll
            for (int it = 0; it < 8; it++) {
                int idx = tid + it * 256;
                int c = idx >> 5, d4 = (idx & 31) * 4;
                *(float4*)&sV[c * 128 + d4] = *(const float4*)&vp[(size_t)c * 1024 + d4];
            }
        }
        __syncthreads();

        // S = Q K^T for both components
        float s1[4][4], s2[4][4];
#pragma unroll
        for (int i = 0; i < 4; i++)
#pragma unroll
            for (int j = 0; j < 4; j++) { s1[i][j] = 0.0f; s2[i][j] = 0.0f; }
        const float* q1b = sQ + ty * 4;
        const float* q2b = sQ + 4352 + ty * 4;
        const float* k1b = sKP + tx * 4;
        const float* k2b = sKP + 4352 + tx * 4;
#pragma unroll 2
        for (int d = 0; d < 64; d++) {
            float4 qa = *(const float4*)(q1b + d * 68);
            float4 ka = *(const float4*)(k1b + d * 68);
            float4 qb = *(const float4*)(q2b + d * 68);
            float4 kb = *(const float4*)(k2b + d * 68);
            float qv1[4] = {qa.x, qa.y, qa.z, qa.w};
            float kv1[4] = {ka.x, ka.y, ka.z, ka.w};
            float qv2[4] = {qb.x, qb.y, qb.z, qb.w};
            float kv2[4] = {kb.x, kb.y, kb.z, kb.w};
#pragma unroll
            for (int i = 0; i < 4; i++)
#pragma unroll
                for (int j = 0; j < 4; j++) {
                    s1[i][j] = fmaf(qv1[i], kv1[j], s1[i][j]);
                    s2[i][j] = fmaf(qv2[i], kv2[j], s2[i][j]);
                }
        }
        __syncthreads();   // done reading K; sKP will hold P now

        const bool diag = (kt == qt);
        softmax_update(s1, m1, l1, acc1, diag, q0 + ty * 4, k0 + tx * 4);
        softmax_update(s2, m2, l2, acc2, diag, q0 + ty * 4, k0 + tx * 4);

        // write P (row-major, stride 65)
#pragma unroll
        for (int i = 0; i < 4; i++)
#pragma unroll
            for (int j = 0; j < 4; j++) {
                sKP[(ty * 4 + i) * 65 + tx * 4 + j] = s1[i][j];
                sKP[4160 + (ty * 4 + i) * 65 + tx * 4 + j] = s2[i][j];
            }
        __syncthreads();

        // O += P V  (both components share V)
#pragma unroll 2
        for (int c = 0; c < 64; c++) {
            float4 v0 = *(const float4*)&sV[c * 128 + tx * 8];
            float4 v1 = *(const float4*)&sV[c * 128 + tx * 8 + 4];
            float vv[8] = {v0.x, v0.y, v0.z, v0.w, v1.x, v1.y, v1.z, v1.w};
#pragma unroll
            for (int i = 0; i < 4; i++) {
                float p1 = sKP[(ty * 4 + i) * 65 + c];
                float p2 = sKP[4160 + (ty * 4 + i) * 65 + c];
#pragma unroll
                for (int jj = 0; jj < 8; jj++) {
                    acc1[i][jj] = fmaf(p1, vv[jj], acc1[i][jj]);
                    acc2[i][jj] = fmaf(p2, vv[jj], acc2[i][jj]);
                }
            }
        }
    }

    // epilogue: diff, RMS over 128, subln weight, (1 - lambda_init)
#pragma unroll
    for (int i = 0; i < 4; i++) {
        float inv1 = 1.0f / l1[i];
        float inv2 = 1.0f / l2[i];
        float a[8];
        float ss = 0.0f;
#pragma unroll
        for (int jj = 0; jj < 8; jj++) {
            a[jj] = acc1[i][jj] * inv1 - lam * (acc2[i][jj] * inv2);
            ss = fmaf(a[jj], a[jj], ss);
        }
        ss += __shfl_xor_sync(0xffffffffu, ss, 1);
        ss += __shfl_xor_sync(0xffffffffu, ss, 2);
        ss += __shfl_xor_sync(0xffffffffu, ss, 4);
        ss += __shfl_xor_sync(0xffffffffu, ss, 8);
        float rinv = rsqrtf(ss * (1.0f / 128.0f) + 1e-5f);
        float* op = g_a + (size_t)(b * S_ + q0 + ty * 4 + i) * 2048 + h * 128 + tx * 8;
        float o[8];
#pragma unroll
        for (int jj = 0; jj < 8; jj++)
            o[jj] = a[jj] * rinv * subw[tx * 8 + jj] * ONE_MINUS_LI;
        *(float4*)op       = make_float4(o[0], o[1], o[2], o[3]);
        *(float4*)(op + 4) = make_float4(o[4], o[5], o[6], o[7]);
    }
}

// ---------------- launch ----------------
extern "C" void kernel_launch(void* const* d_in, const int* in_sizes, int n_in,
                              void* d_out, int out_size) {
    const float* x    = (const float*)d_in[0];
    const float* cosb = (const float*)d_in[1];
    const float* sinb = (const float*)d_in[2];
    const float* Wq   = (const float*)d_in[3];
    const float* Wk   = (const float*)d_in[4];
    const float* Wv   = (const float*)d_in[5];
    const float* Wo   = (const float*)d_in[6];
    const float* lq1  = (const float*)d_in[7];
    const float* lk1  = (const float*)d_in[8];
    const float* lq2  = (const float*)d_in[9];
    const float* lk2  = (const float*)d_in[10];
    const float* subw = (const float*)d_in[11];
    float* out = (float*)d_out;

    float *qp, *kp, *vp, *ap;
    cudaGetSymbolAddress((void**)&qp, g_q);
    cudaGetSymbolAddress((void**)&kp, g_k);
    cudaGetSymbolAddress((void**)&vp, g_v);
    cudaGetSymbolAddress((void**)&ap, g_a);

    cudaFuncSetAttribute(diffattn_kernel,
                         cudaFuncAttributeMaxDynamicSharedMemorySize, 102400);

    dim3 blk(256);
    // projections
    sgemm_nt<<<dim3(16, 32), blk>>>(x, Wq, qp, M_, 2048, 2048);
    sgemm_nt<<<dim3(8, 32),  blk>>>(x, Wk, kp, M_, 1024, 2048);
    sgemm_nt<<<dim3(8, 32),  blk>>>(x, Wv, vp, M_, 1024, 2048);
    // rotary on q and k
    rope_kernel<<<(QPAIRS + KPAIRS + 255) / 256, 256>>>(cosb, sinb);
    // lambda scalar
    lam_kernel<<<1, 64>>>(lq1, lk1, lq2, lk2);
    // dual causal attention + diff + RMS norm
    diffattn_kernel<<<dim3(S_ / 64, H_, B_), 256, 102400>>>(subw);
    // output projection
    sgemm_nt<<<dim3(16, 32), blk>>>(ap, Wo, out, M_, 2048, 2048);
}

// round 7
// speedup vs baseline: 1.3276x; 1.3276x over previous
#include <cuda_runtime.h>
#include <cuda_bf16.h>
#include <cstdint>

// ---------------- problem constants ----------------
#define B_    2
#define S_    2048
#define E_    2048
#define H_    16
#define HKV_  8
#define D_    64
#define M_    (B_ * S_)            // 4096 token rows
#define LAMBDA_INIT_F 0.78360576653f
#define ONE_MINUS_LI  0.21639423347f
#define SCALE_F       0.125f

// ---------------- scratch (device globals: no allocations allowed) ----------------
__device__ float g_q[M_ * 2048];   // (B,S,2H,D)
__device__ float g_k[M_ * 1024];   // (B,S,2HKV,D)
__device__ float g_v[M_ * 1024];   // (B,S,HKV,2D)
__device__ float g_a[M_ * 2048];   // normalized diff-attn output (B,S,E)
__device__ float g_lam;

// ---------------- helpers ----------------
__device__ __forceinline__ uint32_t smem_u32(const void* p) {
    uint32_t a;
    asm("{ .reg .u64 t; cvta.to.shared.u64 t, %1; cvt.u32.u64 %0, t; }" : "=r"(a) : "l"(p));
    return a;
}
__device__ __forceinline__ void cvt_pair(float x, float y, uint32_t& hp, uint32_t& lp) {
    __nv_bfloat16 hx = __float2bfloat16_rn(x);
    __nv_bfloat16 hy = __float2bfloat16_rn(y);
    float lx = x - __bfloat162float(hx);
    float ly = y - __bfloat162float(hy);
    hp = ((uint32_t)__bfloat16_as_ushort(hy) << 16) | (uint32_t)__bfloat16_as_ushort(hx);
    __nv_bfloat162 l2 = __floats2bfloat162_rn(lx, ly);
    lp = *reinterpret_cast<uint32_t*>(&l2);
}

#define LDSM4(r, a) \
    asm volatile("ldmatrix.sync.aligned.m8n8.x4.shared.b16 {%0,%1,%2,%3}, [%4];" \
        : "=r"((r)[0]), "=r"((r)[1]), "=r"((r)[2]), "=r"((r)[3]) : "r"(a))

#define MMA16816(c, a, b) \
    asm volatile("mma.sync.aligned.m16n8k16.row.col.f32.bf16.bf16.f32 " \
        "{%0,%1,%2,%3}, {%4,%5,%6,%7}, {%8,%9}, {%0,%1,%2,%3};" \
        : "+f"((c)[0]), "+f"((c)[1]), "+f"((c)[2]), "+f"((c)[3]) \
        : "r"((a)[0]), "r"((a)[1]), "r"((a)[2]), "r"((a)[3]), "r"((b)[0]), "r"((b)[1]))

// ---------------- HMMA GEMM: C[M,N] = A[M,K] @ W[N,K]^T (fp32 via bf16 hi/lo split) ----
// BM=BN=128, BK=32, 256 threads (8 warps, 2x4). Per stage: Ah|Al|Wh|Wl planes,
// each plane [128 rows][40 bf16] (80 B rows, 16B-aligned, ldmatrix conflict-free).
#define GM_PLANE  10240
#define GM_STAGE  40960
#define GM_SMEM   (2 * GM_STAGE)   // 81920

__global__ void __launch_bounds__(256, 1)
gemm_mma(const float* __restrict__ A, const float* __restrict__ W,
         float* __restrict__ C, int M, int N, int K) {
    extern __shared__ char smem[];
    const uint32_t sb0 = smem_u32(smem);
    const int tid = threadIdx.x, lane = tid & 31, wid = tid >> 5;
    const int wm = wid >> 2, wn = wid & 3;
    const int bm = blockIdx.y * 128, bn = blockIdx.x * 128;

    // gmem staging: thread handles row tid>>1, 16 cols starting (tid&1)*16
    const int srow = tid >> 1, scol = (tid & 1) * 16;
    const float* Ab = A + (size_t)(bm + srow) * K + scol;
    const float* Wb = W + (size_t)(bn + srow) * K + scol;
    const uint32_t soff = (uint32_t)(srow * 80 + scol * 2);

    // ldmatrix per-thread base offsets (bytes)
    const uint32_t aoff = (uint32_t)((wm * 64 + ((lane >> 3) & 1) * 8 + (lane & 7)) * 80 +
                                     ((lane >> 4) & 1) * 16);
    const uint32_t boff = (uint32_t)((wn * 32 + ((lane >> 4) & 1) * 8 + (lane & 7)) * 80 +
                                     ((lane >> 3) & 1) * 16);

    float c[4][4][4];
#pragma unroll
    for (int i = 0; i < 4; i++)
#pragma unroll
        for (int j = 0; j < 4; j++)
#pragma unroll
            for (int q = 0; q < 4; q++) c[i][j][q] = 0.0f;

    // prefetch chunk 0
    float4 pa[4], pw[4];
#pragma unroll
    for (int i = 0; i < 4; i++) {
        pa[i] = *(const float4*)(Ab + i * 4);
        pw[i] = *(const float4*)(Wb + i * 4);
    }

    const int nch = K >> 5;   // 64
    for (int cidx = 0; cidx < nch; cidx++) {
        const int st = cidx & 1;
        char* s = smem + st * GM_STAGE;
        __syncthreads();   // stage free (compute cidx-2 done)
        // convert + store current chunk
        {
            uint32_t h[8], l[8];
#pragma unroll
            for (int i = 0; i < 4; i++) {
                cvt_pair(pa[i].x, pa[i].y, h[2 * i], l[2 * i]);
                cvt_pair(pa[i].z, pa[i].w, h[2 * i + 1], l[2 * i + 1]);
            }
            *(uint4*)(s + soff)              = make_uint4(h[0], h[1], h[2], h[3]);
            *(uint4*)(s + soff + 16)         = make_uint4(h[4], h[5], h[6], h[7]);
            *(uint4*)(s + GM_PLANE + soff)      = make_uint4(l[0], l[1], l[2], l[3]);
            *(uint4*)(s + GM_PLANE + soff + 16) = make_uint4(l[4], l[5], l[6], l[7]);
#pragma unroll
            for (int i = 0; i < 4; i++) {
                cvt_pair(pw[i].x, pw[i].y, h[2 * i], l[2 * i]);
                cvt_pair(pw[i].z, pw[i].w, h[2 * i + 1], l[2 * i + 1]);
            }
            *(uint4*)(s + 2 * GM_PLANE + soff)      = make_uint4(h[0], h[1], h[2], h[3]);
            *(uint4*)(s + 2 * GM_PLANE + soff + 16) = make_uint4(h[4], h[5], h[6], h[7]);
            *(uint4*)(s + 3 * GM_PLANE + soff)      = make_uint4(l[0], l[1], l[2], l[3]);
            *(uint4*)(s + 3 * GM_PLANE + soff + 16) = make_uint4(l[4], l[5], l[6], l[7]);
        }
        // prefetch next chunk (overlaps with compute below)
        if (cidx + 1 < nch) {
            const float* an = Ab + (cidx + 1) * 32;
            const float* wn2 = Wb + (cidx + 1) * 32;
#pragma unroll
            for (int i = 0; i < 4; i++) {
                pa[i] = *(const float4*)(an + i * 4);
                pw[i] = *(const float4*)(wn2 + i * 4);
            }
        }
        __syncthreads();

        const uint32_t sA  = sb0 + st * GM_STAGE;
        const uint32_t sAl = sA + GM_PLANE;
        const uint32_t sW  = sA + 2 * GM_PLANE;
        const uint32_t sWl = sA + 3 * GM_PLANE;
#pragma unroll
        for (int ks = 0; ks < 2; ks++) {
            uint32_t ah[4][4], al[4][4], bh[4][2], bl[4][2];
#pragma unroll
            for (int mt = 0; mt < 4; mt++) {
                LDSM4(ah[mt], sA  + aoff + mt * 1280 + ks * 32);
                LDSM4(al[mt], sAl + aoff + mt * 1280 + ks * 32);
            }
#pragma unroll
            for (int p = 0; p < 2; p++) {
                uint32_t r[4];
                LDSM4(r, sW + boff + p * 1280 + ks * 32);
                bh[2 * p][0] = r[0]; bh[2 * p][1] = r[1];
                bh[2 * p + 1][0] = r[2]; bh[2 * p + 1][1] = r[3];
                LDSM4(r, sWl + boff + p * 1280 + ks * 32);
                bl[2 * p][0] = r[0]; bl[2 * p][1] = r[1];
                bl[2 * p + 1][0] = r[2]; bl[2 * p + 1][1] = r[3];
            }
#pragma unroll
            for (int mt = 0; mt < 4; mt++)
#pragma unroll
                for (int nt = 0; nt < 4; nt++) {
                    MMA16816(c[mt][nt], ah[mt], bh[nt]);
                    MMA16816(c[mt][nt], ah[mt], bl[nt]);
                    MMA16816(c[mt][nt], al[mt], bh[nt]);
                }
        }
    }

    // epilogue
    const int r0 = bm + wm * 64 + (lane >> 2);
    const int c0 = bn + wn * 32 + (lane & 3) * 2;
#pragma unroll
    for (int mt = 0; mt < 4; mt++)
#pragma unroll
        for (int nt = 0; nt < 4; nt++) {
            float* p0 = C + (size_t)(r0 + mt * 16) * N + c0 + nt * 8;
            float* p1 = p0 + 8 * N;
            *(float2*)p0 = make_float2(c[mt][nt][0], c[mt][nt][1]);
            *(float2*)p1 = make_float2(c[mt][nt][2], c[mt][nt][3]);
        }
}

// ---------------- fast exp (FMA pipe, no MUFU) ----------------
__device__ __forceinline__ float fexp(float x) {
    x = fmaxf(x, -80.0f);
    float y  = x * 1.44269504088896f;
    float t  = y + 12582912.0f;
    int   e  = __float_as_int(t);
    float f  = y - (t - 12582912.0f);
    float p  = 1.33335581e-3f;
    p = fmaf(p, f, 9.61812911e-3f);
    p = fmaf(p, f, 5.55041087e-2f);
    p = fmaf(p, f, 2.40226507e-1f);
    p = fmaf(p, f, 6.93147181e-1f);
    p = fmaf(p, f, 1.0f);
    return __int_as_float(__float_as_int(p) + (e << 23));
}

// ---------------- interleaved RoPE on q (32 heads) and k (16 heads), in place ----------------
#define QPAIRS (M_ * 32 * 32)
#define KPAIRS (M_ * 16 * 32)
__global__ void rope_kernel(const float* __restrict__ cosb, const float* __restrict__ sinb) {
    int idx = blockIdx.x * blockDim.x + threadIdx.x;
    if (idx < QPAIRS) {
        int i = idx & 31;
        int head = (idx >> 5) & 31;
        int t = idx >> 10;
        int s = t & (S_ - 1);
        float c = cosb[s * 32 + i], sn = sinb[s * 32 + i];
        float* p = g_q + (size_t)t * 2048 + head * 64 + 2 * i;
        float x1 = p[0], x2 = p[1];
        p[0] = x1 * c - x2 * sn;
        p[1] = x1 * sn + x2 * c;
    } else if (idx < QPAIRS + KPAIRS) {
        int j = idx - QPAIRS;
        int i = j & 31;
        int head = (j >> 5) & 15;
        int t = j >> 9;
        int s = t & (S_ - 1);
        float c = cosb[s * 32 + i], sn = sinb[s * 32 + i];
        float* p = g_k + (size_t)t * 1024 + head * 64 + 2 * i;
        float x1 = p[0], x2 = p[1];
        p[0] = x1 * c - x2 * sn;
        p[1] = x1 * sn + x2 * c;
    }
}

// ---------------- lambda scalar ----------------
__global__ void lam_kernel(const float* __restrict__ lq1, const float* __restrict__ lk1,
                           const float* __restrict__ lq2, const float* __restrict__ lk2) {
    __shared__ float s1a[2], s2a[2];
    int t = threadIdx.x;   // 64 threads
    float p1 = lq1[t] * lk1[t];
    float p2 = lq2[t] * lk2[t];
#pragma unroll
    for (int o = 16; o > 0; o >>= 1) {
        p1 += __shfl_xor_sync(0xffffffffu, p1, o);
        p2 += __shfl_xor_sync(0xffffffffu, p2, o);
    }
    if ((t & 31) == 0) { s1a[t >> 5] = p1; s2a[t >> 5] = p2; }
    __syncthreads();
    if (t == 0)
        g_lam = expf(s1a[0] + s1a[1]) - expf(s2a[0] + s2a[1]) + LAMBDA_INIT_F;
}

// ---------------- dual-component causal flash attention + diff + RMS-subln ----------------
__device__ __forceinline__ void softmax_update(float s[4][4], float m[4], float l[4],
                                               float acc[4][8], bool diag,
                                               int qrow0, int kcol0) {
#pragma unroll
    for (int i = 0; i < 4; i++) {
        float rowm = -1e30f;
#pragma unroll
        for (int j = 0; j < 4; j++) {
            float v = s[i][j] * SCALE_F;
            if (diag && (kcol0 + j > qrow0 + i)) v = -1e30f;
            s[i][j] = v;
            rowm = fmaxf(rowm, v);
        }
        rowm = fmaxf(rowm, __shfl_xor_sync(0xffffffffu, rowm, 1));
        rowm = fmaxf(rowm, __shfl_xor_sync(0xffffffffu, rowm, 2));
        rowm = fmaxf(rowm, __shfl_xor_sync(0xffffffffu, rowm, 4));
        rowm = fmaxf(rowm, __shfl_xor_sync(0xffffffffu, rowm, 8));
        float mnew = fmaxf(m[i], rowm);
        float corr = fexp(m[i] - mnew);
        m[i] = mnew;
        float rs = 0.0f;
#pragma unroll
        for (int j = 0; j < 4; j++) {
            float p = fexp(s[i][j] - mnew);
            s[i][j] = p;
            rs += p;
        }
        rs += __shfl_xor_sync(0xffffffffu, rs, 1);
        rs += __shfl_xor_sync(0xffffffffu, rs, 2);
        rs += __shfl_xor_sync(0xffffffffu, rs, 4);
        rs += __shfl_xor_sync(0xffffffffu, rs, 8);
        l[i] = l[i] * corr + rs;
#pragma unroll
        for (int jj = 0; jj < 8; jj++) acc[i][jj] *= corr;
    }
}

__global__ void __launch_bounds__(256, 1)
diffattn_kernel(const float* __restrict__ subw) {
    extern __shared__ float fsmem[];
    float* sQ  = fsmem;
    float* sKP = fsmem + 8704;
    float* sV  = fsmem + 17408;

    const int qt = blockIdx.x, h = blockIdx.y, b = blockIdx.z;
    const int q0 = qt * 64;
    const int kvh = h >> 1;
    const int tid = threadIdx.x;
    const int tx = tid & 15, ty = tid >> 4;
    const float lam = g_lam;

#pragma unroll
    for (int comp = 0; comp < 2; comp++) {
        const float* qp = g_q + (size_t)(b * S_ + q0) * 2048 + (2 * h + comp) * 64;
#pragma unroll
        for (int it = 0; it < 16; it++) {
            int idx = tid + it * 256;
            int r = idx >> 6, d = idx & 63;
            sQ[comp * 4352 + d * 68 + r] = qp[(size_t)r * 2048 + d];
        }
    }

    float acc1[4][8], acc2[4][8];
    float m1[4], l1[4], m2[4], l2[4];
#pragma unroll
    for (int i = 0; i < 4; i++) {
        m1[i] = m2[i] = -1e30f;
        l1[i] = l2[i] = 0.0f;
#pragma unroll
        for (int jj = 0; jj < 8; jj++) { acc1[i][jj] = 0.0f; acc2[i][jj] = 0.0f; }
    }

    for (int kt = 0; kt <= qt; kt++) {
        const int k0 = kt * 64;
        __syncthreads();
#pragma unroll
        for (int comp = 0; comp < 2; comp++) {
            const float* kp = g_k + (size_t)(b * S_ + k0) * 1024 + (2 * kvh + comp) * 64;
#pragma unroll
            for (int it = 0; it < 16; it++) {
                int idx = tid + it * 256;
                int c = idx >> 6, d = idx & 63;
                sKP[comp * 4352 + d * 68 + c] = kp[(size_t)c * 1024 + d];
            }
        }
        {
            const float* vp = g_v + (size_t)(b * S_ + k0) * 1024 + kvh * 128;
#pragma unroll
            for (int it = 0; it < 8; it++) {
                int idx = tid + it * 256;
                int c = idx >> 5, d4 = (idx & 31) * 4;
                *(float4*)&sV[c * 128 + d4] = *(const float4*)&vp[(size_t)c * 1024 + d4];
            }
        }
        __syncthreads();

        float s1[4][4], s2[4][4];
#pragma unroll
        for (int i = 0; i < 4; i++)
#pragma unroll
            for (int j = 0; j < 4; j++) { s1[i][j] = 0.0f; s2[i][j] = 0.0f; }
        const float* q1b = sQ + ty * 4;
        const float* q2b = sQ + 4352 + ty * 4;
        const float* k1b = sKP + tx * 4;
        const float* k2b = sKP + 4352 + tx * 4;
#pragma unroll 2
        for (int d = 0; d < 64; d++) {
            float4 qa = *(const float4*)(q1b + d * 68);
            float4 ka = *(const float4*)(k1b + d * 68);
            float4 qb = *(const float4*)(q2b + d * 68);
            float4 kb = *(const float4*)(k2b + d * 68);
            float qv1[4] = {qa.x, qa.y, qa.z, qa.w};
            float kv1[4] = {ka.x, ka.y, ka.z, ka.w};
            float qv2[4] = {qb.x, qb.y, qb.z, qb.w};
            float kv2[4] = {kb.x, kb.y, kb.z, kb.w};
#pragma unroll
            for (int i = 0; i < 4; i++)
#pragma unroll
                for (int j = 0; j < 4; j++) {
                    s1[i][j] = fmaf(qv1[i], kv1[j], s1[i][j]);
                    s2[i][j] = fmaf(qv2[i], kv2[j], s2[i][j]);
                }
        }
        __syncthreads();

        const bool diag = (kt == qt);
        softmax_update(s1, m1, l1, acc1, diag, q0 + ty * 4, k0 + tx * 4);
        softmax_update(s2, m2, l2, acc2, diag, q0 + ty * 4, k0 + tx * 4);

#pragma unroll
        for (int i = 0; i < 4; i++)
#pragma unroll
            for (int j = 0; j < 4; j++) {
                sKP[(ty * 4 + i) * 65 + tx * 4 + j] = s1[i][j];
                sKP[4160 + (ty * 4 + i) * 65 + tx * 4 + j] = s2[i][j];
            }
        __syncthreads();

#pragma unroll 2
        for (int c = 0; c < 64; c++) {
            float4 v0 = *(const float4*)&sV[c * 128 + tx * 8];
            float4 v1 = *(const float4*)&sV[c * 128 + tx * 8 + 4];
            float vv[8] = {v0.x, v0.y, v0.z, v0.w, v1.x, v1.y, v1.z, v1.w};
#pragma unroll
            for (int i = 0; i < 4; i++) {
                float p1 = sKP[(ty * 4 + i) * 65 + c];
                float p2 = sKP[4160 + (ty * 4 + i) * 65 + c];
#pragma unroll
                for (int jj = 0; jj < 8; jj++) {
                    acc1[i][jj] = fmaf(p1, vv[jj], acc1[i][jj]);
                    acc2[i][jj] = fmaf(p2, vv[jj], acc2[i][jj]);
                }
            }
        }
    }

#pragma unroll
    for (int i = 0; i < 4; i++) {
        float inv1 = 1.0f / l1[i];
        float inv2 = 1.0f / l2[i];
        float a[8];
        float ss = 0.0f;
#pragma unroll
        for (int jj = 0; jj < 8; jj++) {
            a[jj] = acc1[i][jj] * inv1 - lam * (acc2[i][jj] * inv2);
            ss = fmaf(a[jj], a[jj], ss);
        }
        ss += __shfl_xor_sync(0xffffffffu, ss, 1);
        ss += __shfl_xor_sync(0xffffffffu, ss, 2);
        ss += __shfl_xor_sync(0xffffffffu, ss, 4);
        ss += __shfl_xor_sync(0xffffffffu, ss, 8);
        float rinv = rsqrtf(ss * (1.0f / 128.0f) + 1e-5f);
        float* op = g_a + (size_t)(b * S_ + q0 + ty * 4 + i) * 2048 + h * 128 + tx * 8;
        float o[8];
#pragma unroll
        for (int jj = 0; jj < 8; jj++)
            o[jj] = a[jj] * rinv * subw[tx * 8 + jj] * ONE_MINUS_LI;
        *(float4*)op       = make_float4(o[0], o[1], o[2], o[3]);
        *(float4*)(op + 4) = make_float4(o[4], o[5], o[6], o[7]);
    }
}

// ---------------- launch ----------------
extern "C" void kernel_launch(void* const* d_in, const int* in_sizes, int n_in,
                              void* d_out, int out_size) {
    const float* x    = (const float*)d_in[0];
    const float* cosb = (const float*)d_in[1];
    const float* sinb = (const float*)d_in[2];
    const float* Wq   = (const float*)d_in[3];
    const float* Wk   = (const float*)d_in[4];
    const float* Wv   = (const float*)d_in[5];
    const float* Wo   = (const float*)d_in[6];
    const float* lq1  = (const float*)d_in[7];
    const float* lk1  = (const float*)d_in[8];
    const float* lq2  = (const float*)d_in[9];
    const float* lk2  = (const float*)d_in[10];
    const float* subw = (const float*)d_in[11];
    float* out = (float*)d_out;

    float *qp, *kp, *vp, *ap;
    cudaGetSymbolAddress((void**)&qp, g_q);
    cudaGetSymbolAddress((void**)&kp, g_k);
    cudaGetSymbolAddress((void**)&vp, g_v);
    cudaGetSymbolAddress((void**)&ap, g_a);

    cudaFuncSetAttribute(gemm_mma, cudaFuncAttributeMaxDynamicSharedMemorySize, GM_SMEM);
    cudaFuncSetAttribute(diffattn_kernel, cudaFuncAttributeMaxDynamicSharedMemorySize, 102400);

    dim3 blk(256);
    // projections on tensor cores (HMMA, bf16 hi/lo split, fp32 accumulate)
    gemm_mma<<<dim3(16, 32), blk, GM_SMEM>>>(x, Wq, qp, M_, 2048, 2048);
    gemm_mma<<<dim3(8, 32),  blk, GM_SMEM>>>(x, Wk, kp, M_, 1024, 2048);
    gemm_mma<<<dim3(8, 32),  blk, GM_SMEM>>>(x, Wv, vp, M_, 1024, 2048);
    // rotary on q and k
    rope_kernel<<<(QPAIRS + KPAIRS + 255) / 256, 256>>>(cosb, sinb);
    // lambda scalar
    lam_kernel<<<1, 64>>>(lq1, lk1, lq2, lk2);
    // dual causal attention + diff + RMS norm
    diffattn_kernel<<<dim3(S_ / 64, H_, B_), 256, 102400>>>(subw);
    // output projection
    gemm_mma<<<dim3(16, 32), blk, GM_SMEM>>>(ap, Wo, out, M_, 2048, 2048);
}